// round 16
// baseline (speedup 1.0000x reference)
#include <cuda_runtime.h>

#define Bb 8
#define Nn 4096
#define NC 13
#define BN (Bb*Nn)        // 32768 points per set
#define TPB 128
#define QPT 4
#define QPB (TPB*QPT)     // 512 queries (rec rows) per block
#define CSN 32            // candidate slices per batch
#define SC (Nn/CSN)       // 128 candidates (pt cols) per block
#define SP (SC/2)         // 64 candidate pairs
#define NBLK (Bb*8*CSN)   // 2048
#define NRG (Bb*8)        // 64 row groups (b,qblk), 32 arrivals
#define NCG (Bb*CSN)      // 256 col groups (b,cs), 8 arrivals
#define DUMP 320          // per-warp garbage-store region (u64 slots)
#define ENC 0x7F800000    // k = ENC - float_bits(d); 0 == +inf; min d == max k
#define INFF 3.4e38f

typedef unsigned long long u64;

__device__ int          g_rmin[BN];      // encoded row mins (rec->pt); 0==+inf; leader-reset
__device__ int          g_cmin[BN];      // encoded col mins (pt->rec)
__device__ float        g_rowpart[NRG];
__device__ float        g_colpart[NCG];
__device__ float        g_fpart[NBLK];   // per-block seg sums
__device__ unsigned int g_rowtk[NRG];    // zero-init; self-reset
__device__ unsigned int g_coltk[NCG];
__device__ unsigned int g_ticket;        // counts row+col leaders = NRG+NCG

// ---- f32x2 helpers ----------------------------------------------------------
__device__ __forceinline__ u64 pk(float lo, float hi) {
    u64 r; asm("mov.b64 %0, {%1, %2};" : "=l"(r) : "f"(lo), "f"(hi)); return r;
}
__device__ __forceinline__ u64 fma2(u64 a, u64 b, u64 c) {
    u64 d; asm("fma.rn.f32x2 %0, %1, %2, %3;" : "=l"(d) : "l"(a), "l"(b), "l"(c)); return d;
}
__device__ __forceinline__ u64 add2(u64 a, u64 b) {
    u64 d; asm("add.rn.f32x2 %0, %1, %2;" : "=l"(d) : "l"(a), "l"(b)); return d;
}
__device__ __forceinline__ void upk(u64 v, float& lo, float& hi) {
    asm("mov.b64 {%0, %1}, %2;" : "=f"(lo), "=f"(hi) : "l"(v));
}

// ---- single fused symmetric kernel -------------------------------------------
// grid (CSN, 8, Bb) = (32,8,8): x = cand slice, y = qblk, z = batch
__global__ void __launch_bounds__(TPB, 7) fused_kernel(const float* __restrict__ rec,
                                                       const float* __restrict__ pt,
                                                       const float* __restrict__ prob,
                                                       const void* __restrict__ lab,
                                                       float* __restrict__ out) {
    __shared__ ulonglong2 scd[SC];          // 2KB: SP pairs x 2 entries
    __shared__ u64        scolp[4*SP*4];    // 8KB: 4 partial col-min pairs per (warp,jp)
    __shared__ u64        sdump[4*DUMP];    // 10KB: garbage sink (branch-free STS)
    __shared__ float      sred[TPB];
    __shared__ int        s_is64, s_rowfin, s_colfin, s_last;

    const int cs   = blockIdx.x;
    const int qblk = blockIdx.y;
    const int b    = blockIdx.z;
    const int t    = threadIdx.x;
    const int w    = t >> 5;
    const int lane = t & 31;
    const int bl   = (b * 8 + qblk) * CSN + cs;   // [0,2048)
    const int rowg = b * 8 + qblk;                // [0,64)
    const int colg = b * CSN + cs;                // [0,256)

    if (t == 0) { s_is64 = 1; s_rowfin = 0; s_colfin = 0; s_last = 0; }
    __syncthreads();
    // labels < 13; if int64 every odd 32-bit word is 0 (probe 128 labels)
    if (((const int*)lab)[2 * t + 1] != 0) s_is64 = 0;

    // queries = rec rows: pack dup(-2x/-2y/-2z) and dup(qn)
    const int qbase = b * Nn + qblk * QPB;
    u64 qx2[QPT], qy2[QPT], qz2[QPT], qn2[QPT];
    #pragma unroll
    for (int k = 0; k < QPT; k++) {
        const float* p = rec + (size_t)(qbase + t + k * TPB) * 3;
        float x = p[0], y = p[1], z = p[2];
        float n = fmaf(x, x, fmaf(y, y, z * z));
        qx2[k] = pk(-2.f * x, -2.f * x);
        qy2[k] = pk(-2.f * y, -2.f * y);
        qz2[k] = pk(-2.f * z, -2.f * z);
        qn2[k] = pk(n, n);
    }

    // candidates = pt cols: stage + pack one pair per thread (t < SP)
    if (t < SP) {
        const int cbase = b * Nn + cs * SC;
        const float* c = pt + (size_t)(cbase + 2 * t) * 3;
        float x0 = c[0], y0 = c[1], z0 = c[2];
        float x1 = c[3], y1 = c[4], z1 = c[5];
        float n0 = fmaf(x0, x0, fmaf(y0, y0, z0 * z0));
        float n1 = fmaf(x1, x1, fmaf(y1, y1, z1 * z1));
        scd[2 * t]     = make_ulonglong2(pk(x0, x1), pk(y0, y1));
        scd[2 * t + 1] = make_ulonglong2(pk(z0, z1), pk(n0, n1));
    }
    __syncthreads();

    // branch-free col-min store target: lanes 0/8/16/24 -> real slot g=lane>>3,
    // all other lanes -> garbage sink (distinct banks; races harmless)
    u64* sbase = ((lane & 7) == 0) ? &scolp[w * SP * 4 + (lane >> 3)]
                                   : &sdump[w * DUMP + lane];

    float m0 = INFF, m1 = INFF, m2 = INFF, m3 = INFF;
    // software prefetch: candidate pair for jp resides in regs before iteration
    ulonglong2 c0 = scd[0];
    ulonglong2 c1 = scd[1];
    #pragma unroll 4
    for (int jp = 0; jp < SP; jp++) {
        ulonglong2 p0 = c0;               // {cx,cx'},{cy,cy'}
        ulonglong2 p1 = c1;               // {cz,cz'},{cn,cn'}
        int nxt = (jp + 1) & (SP - 1);    // wraps to 0 on last iter (harmless reload)
        c0 = scd[2 * nxt];
        c1 = scd[2 * nxt + 1];
        // full distances: d = qn + cn - 2 q.c  (qn folded for column comparability)
        u64 t0 = fma2(qx2[0], p0.x, fma2(qy2[0], p0.y, fma2(qz2[0], p1.x, add2(p1.y, qn2[0]))));
        u64 t1 = fma2(qx2[1], p0.x, fma2(qy2[1], p0.y, fma2(qz2[1], p1.x, add2(p1.y, qn2[1]))));
        u64 t2 = fma2(qx2[2], p0.x, fma2(qy2[2], p0.y, fma2(qz2[2], p1.x, add2(p1.y, qn2[2]))));
        u64 t3 = fma2(qx2[3], p0.x, fma2(qy2[3], p0.y, fma2(qz2[3], p1.x, add2(p1.y, qn2[3]))));
        float l0, h0, l1, h1, l2, h2, l3, h3;
        upk(t0, l0, h0); upk(t1, l1, h1); upk(t2, l2, h2); upk(t3, l3, h3);
        // row mins (per query, registers)
        m0 = fminf(m0, fminf(l0, h0));
        m1 = fminf(m1, fminf(l1, h1));
        m2 = fminf(m2, fminf(l2, h2));
        m3 = fminf(m3, fminf(l3, h3));
        // col mins: pre-reduce 4 queries, then 3-level SHFL butterfly -> 8-lane groups
        float cA = fminf(fminf(l0, l1), fminf(l2, l3));
        float cB = fminf(fminf(h0, h1), fminf(h2, h3));
        #pragma unroll
        for (int dlt = 1; dlt < 8; dlt <<= 1) {
            cA = fminf(cA, __shfl_xor_sync(0xffffffffu, cA, dlt));
            cB = fminf(cB, __shfl_xor_sync(0xffffffffu, cB, dlt));
        }
        // unconditional STS (no BSSY/BSYNC): group leaders write real slots
        sbase[jp * 4] = ((u64)__float_as_uint(cB) << 32) | (u64)__float_as_uint(cA);
    }

    // row mins -> global encoded
    {
        int* gm = g_rmin + b * Nn + qblk * QPB;
        atomicMax(gm + t,           ENC - __float_as_int(m0));
        atomicMax(gm + t + TPB,     ENC - __float_as_int(m1));
        atomicMax(gm + t + 2 * TPB, ENC - __float_as_int(m2));
        atomicMax(gm + t + 3 * TPB, ENC - __float_as_int(m3));
    }
    __syncthreads();

    // col mins: combine 4 warps x 4 group-partials; thread t<SP owns pair jp=t
    if (t < SP) {
        float A = INFF, B = INFF;
        #pragma unroll
        for (int w2 = 0; w2 < 4; w2++) {
            #pragma unroll
            for (int g = 0; g < 4; g++) {
                u64 v = scolp[(w2 * SP + t) * 4 + g];
                A = fminf(A, __uint_as_float((unsigned)v));
                B = fminf(B, __uint_as_float((unsigned)(v >> 32)));
            }
        }
        int* gc = g_cmin + b * Nn + cs * SC + 2 * t;
        atomicMax(gc,     ENC - __float_as_int(A));
        atomicMax(gc + 1, ENC - __float_as_int(B));
    }

    // seg NLL: 16 points per block (first half-warp)
    if (t < 16) {
        int idx = bl * 16 + t;
        int lb = s_is64 ? (int)((const long long*)lab)[idx] : ((const int*)lab)[idx];
        float v = prob[idx * NC + lb];
        #pragma unroll
        for (int off = 8; off > 0; off >>= 1)
            v += __shfl_xor_sync(0x0000ffffu, v, off);
        if (t == 0) g_fpart[bl] = v;
    }

    // publish: one gpu fence per block (t0), then group tickets
    __syncthreads();
    if (t == 0) {
        __threadfence();
        if (atomicAdd(&g_rowtk[rowg], 1u) == (unsigned)(CSN - 1)) s_rowfin = 1;
        if (atomicAdd(&g_coltk[colg], 1u) == 7u)                  s_colfin = 1;
    }
    __syncthreads();

    if (s_rowfin) {   // row leader: sum 512 query mins; reset
        int4* base = (int4*)(g_rmin + b * Nn + qblk * QPB);
        int4 v = __ldcg(base + t);
        sred[t] = (__int_as_float(ENC - v.x) + __int_as_float(ENC - v.y)) +
                  (__int_as_float(ENC - v.z) + __int_as_float(ENC - v.w));
        __stcg(base + t, make_int4(0, 0, 0, 0));
        __syncthreads();
        #pragma unroll
        for (int s = 64; s > 0; s >>= 1) {
            if (t < s) sred[t] += sred[t + s];
            __syncthreads();
        }
        if (t == 0) {
            g_rowpart[rowg] = sred[0];
            g_rowtk[rowg] = 0u;
            __threadfence();
            if (atomicAdd(&g_ticket, 1u) == (unsigned)(NRG + NCG - 1)) s_last = 1;
        }
        __syncthreads();
    }
    if (s_colfin) {   // col leader: sum 128 candidate mins; reset
        float acc = 0.f;
        if (t < SC / 4) {
            int4* base = (int4*)(g_cmin + b * Nn + cs * SC);
            int4 v = __ldcg(base + t);
            acc = (__int_as_float(ENC - v.x) + __int_as_float(ENC - v.y)) +
                  (__int_as_float(ENC - v.z) + __int_as_float(ENC - v.w));
            __stcg(base + t, make_int4(0, 0, 0, 0));
        }
        sred[t] = acc;
        __syncthreads();
        #pragma unroll
        for (int s = 64; s > 0; s >>= 1) {
            if (t < s) sred[t] += sred[t + s];
            __syncthreads();
        }
        if (t == 0) {
            g_colpart[colg] = sred[0];
            g_coltk[colg] = 0u;
            __threadfence();
            if (atomicAdd(&g_ticket, 1u) == (unsigned)(NRG + NCG - 1)) s_last = 1;
        }
        __syncthreads();
    }

    __syncthreads();
    if (s_last) {     // final deterministic combine (one block, L2 reads)
        float v = __ldcg(&g_colpart[t]) + __ldcg(&g_colpart[t + TPB]);  // 256 col sums
        if (t < NRG) v += __ldcg(&g_rowpart[t]);                        // 64 row sums
        float sp = 0.f;
        #pragma unroll
        for (int k = 0; k < NBLK / TPB; k++)
            sp += __ldcg(&g_fpart[t + k * TPB]);                        // 2048 seg partials
        sred[t] = v - sp;
        __syncthreads();
        #pragma unroll
        for (int s = 64; s > 0; s >>= 1) {
            if (t < s) sred[t] += sred[t + s];
            __syncthreads();
        }
        if (t == 0) {
            out[0] = sred[0] * (1.0f / (float)BN);
            g_ticket = 0u;   // reset for next graph replay
        }
    }
}

extern "C" void kernel_launch(void* const* d_in, const int* in_sizes, int n_in,
                              void* d_out, int out_size) {
    const float* seg_prob  = (const float*)d_in[0];
    const void*  seg_label = (const void*)d_in[1];
    const float* point_rec = (const float*)d_in[2];
    const float* point     = (const float*)d_in[3];

    fused_kernel<<<dim3(CSN, 8, Bb), TPB>>>(point_rec, point, seg_prob, seg_label,
                                            (float*)d_out);
}

// round 17
// speedup vs baseline: 1.0856x; 1.0856x over previous
#include <cuda_runtime.h>

#define Bb 8
#define Nn 4096
#define NC 13
#define BN (Bb*Nn)        // 32768 points per set
#define TPB 128
#define QPT 8
#define QPB (TPB*QPT)     // 1024 queries (rec rows) per block
#define NQB (Nn/QPB)      // 4 query blocks per batch
#define CSN 32            // candidate slices per batch
#define SC (Nn/CSN)       // 128 candidates (pt cols) per block
#define NBLK (Bb*NQB*CSN) // 1024
#define NRG (Bb*NQB)      // 32 row groups, CSN=32 arrivals
#define NCG (Bb*CSN)      // 256 col groups, NQB=4 arrivals
#define DUMP 32           // per-warp garbage-store region (u32 slots)
#define ENC 0x7F800000    // k = ENC - float_bits(d); 0 == +inf; min d == max k
#define INFF 3.4e38f

typedef unsigned long long u64;

__device__ int          g_rmin[BN];      // encoded row mins (rec->pt); 0==+inf; leader-reset
__device__ int          g_cmin[BN];      // encoded col mins (pt->rec)
__device__ float        g_rowpart[NRG];
__device__ float        g_colpart[NCG];
__device__ float        g_fpart[NBLK];   // per-block seg sums
__device__ unsigned int g_rowtk[NRG];    // zero-init; self-reset
__device__ unsigned int g_coltk[NCG];
__device__ unsigned int g_ticket;        // counts row+col leaders = NRG+NCG

// ---- f32x2 helpers ----------------------------------------------------------
__device__ __forceinline__ u64 pk(float lo, float hi) {
    u64 r; asm("mov.b64 %0, {%1, %2};" : "=l"(r) : "f"(lo), "f"(hi)); return r;
}
__device__ __forceinline__ u64 fma2(u64 a, u64 b, u64 c) {
    u64 d; asm("fma.rn.f32x2 %0, %1, %2, %3;" : "=l"(d) : "l"(a), "l"(b), "l"(c)); return d;
}
__device__ __forceinline__ u64 add2(u64 a, u64 b) {
    u64 d; asm("add.rn.f32x2 %0, %1, %2;" : "=l"(d) : "l"(a), "l"(b)); return d;
}
__device__ __forceinline__ void upk(u64 v, float& lo, float& hi) {
    asm("mov.b64 {%0, %1}, %2;" : "=f"(lo), "=f"(hi) : "l"(v));
}

// ---- single fused symmetric kernel -------------------------------------------
// grid (CSN, NQB, Bb) = (32,4,8): x = cand slice, y = qblk, z = batch
// Layout: 2 queries per f32x2 lane (chain c = queries t+2c*TPB, t+(2c+1)*TPB);
// candidate duplicated -> ONE REDUX per candidate per warp (8 evals/thread/jp).
__global__ void __launch_bounds__(TPB, 7) fused_kernel(const float* __restrict__ rec,
                                                       const float* __restrict__ pt,
                                                       const float* __restrict__ prob,
                                                       const void* __restrict__ lab,
                                                       float* __restrict__ out) {
    __shared__ ulonglong2 scd[2*SC];        // 4KB: cand j -> [2j]={xx,yy} [2j+1]={zz,nn}
    __shared__ unsigned   scolp[4*SC];      // 2KB: per-warp col-min bits
    __shared__ unsigned   sdump[4*DUMP];    // 512B: garbage sink (branch-free STS)
    __shared__ float      sred[TPB];
    __shared__ int        s_is64, s_rowfin, s_colfin, s_last;

    const int cs   = blockIdx.x;
    const int qblk = blockIdx.y;
    const int b    = blockIdx.z;
    const int t    = threadIdx.x;
    const int w    = t >> 5;
    const int lane = t & 31;
    const int bl   = (b * NQB + qblk) * CSN + cs;  // [0,1024)
    const int rowg = b * NQB + qblk;               // [0,32)
    const int colg = b * CSN + cs;                 // [0,256)

    if (t == 0) { s_is64 = 1; s_rowfin = 0; s_colfin = 0; s_last = 0; }
    __syncthreads();
    // labels < 13; if int64 every odd 32-bit word is 0 (probe 128 labels)
    if (((const int*)lab)[2 * t + 1] != 0) s_is64 = 0;

    // queries: chain c packs (-2x,-2x'),(.. y),(.. z),(n,n') for query pair
    const int qbase = b * Nn + qblk * QPB;
    u64 qx2[QPT/2], qy2[QPT/2], qz2[QPT/2], qn2[QPT/2];
    #pragma unroll
    for (int c = 0; c < QPT/2; c++) {
        const float* pa = rec + (size_t)(qbase + t + (2*c)   * TPB) * 3;
        const float* pb = rec + (size_t)(qbase + t + (2*c+1) * TPB) * 3;
        float xa = pa[0], ya = pa[1], za = pa[2];
        float xb = pb[0], yb = pb[1], zb = pb[2];
        float na = fmaf(xa, xa, fmaf(ya, ya, za * za));
        float nb = fmaf(xb, xb, fmaf(yb, yb, zb * zb));
        qx2[c] = pk(-2.f * xa, -2.f * xb);
        qy2[c] = pk(-2.f * ya, -2.f * yb);
        qz2[c] = pk(-2.f * za, -2.f * zb);
        qn2[c] = pk(na, nb);
    }

    // candidates: stage duplicated, one per thread (SC == TPB)
    {
        const float* c = pt + (size_t)(b * Nn + cs * SC + t) * 3;
        float x = c[0], y = c[1], z = c[2];
        float n = fmaf(x, x, fmaf(y, y, z * z));
        scd[2 * t]     = make_ulonglong2(pk(x, x), pk(y, y));
        scd[2 * t + 1] = make_ulonglong2(pk(z, z), pk(n, n));
    }
    __syncthreads();

    // branch-free col-min store target: lane0 -> real slot, others -> garbage
    unsigned* sbase = (lane == 0) ? &scolp[w * SC] : &sdump[w * DUMP + lane];

    float m0 = INFF, m1 = INFF, m2 = INFF, m3 = INFF;
    float m4 = INFF, m5 = INFF, m6 = INFF, m7 = INFF;

    #pragma unroll 2
    for (int j = 0; j < SC; j++) {
        ulonglong2 p0 = scd[2 * j];      // {cx,cx},{cy,cy}
        ulonglong2 p1 = scd[2 * j + 1];  // {cz,cz},{cn,cn}
        u64 t0 = fma2(qx2[0], p0.x, fma2(qy2[0], p0.y, fma2(qz2[0], p1.x, add2(p1.y, qn2[0]))));
        u64 t1 = fma2(qx2[1], p0.x, fma2(qy2[1], p0.y, fma2(qz2[1], p1.x, add2(p1.y, qn2[1]))));
        u64 t2 = fma2(qx2[2], p0.x, fma2(qy2[2], p0.y, fma2(qz2[2], p1.x, add2(p1.y, qn2[2]))));
        u64 t3 = fma2(qx2[3], p0.x, fma2(qy2[3], p0.y, fma2(qz2[3], p1.x, add2(p1.y, qn2[3]))));
        float l0, h0, l1, h1, l2, h2, l3, h3;
        upk(t0, l0, h0); upk(t1, l1, h1); upk(t2, l2, h2); upk(t3, l3, h3);
        // row mins (8 queries)
        m0 = fminf(m0, l0); m1 = fminf(m1, h0);
        m2 = fminf(m2, l1); m3 = fminf(m3, h1);
        m4 = fminf(m4, l2); m5 = fminf(m5, h2);
        m6 = fminf(m6, l3); m7 = fminf(m7, h3);
        // col min: 7 in-thread fminf over the 8 evals, ONE REDUX across lanes
        float cv = fminf(fminf(fminf(l0, h0), fminf(l1, h1)),
                         fminf(fminf(l2, h2), fminf(l3, h3)));
        unsigned ra = __reduce_min_sync(0xffffffffu, __float_as_uint(cv));
        // unconditional STS (no BSSY/BSYNC): lane0 writes real slot, rest hit sink
        sbase[j] = ra;
    }

    // row mins -> global encoded
    {
        int* gm = g_rmin + b * Nn + qblk * QPB + t;
        atomicMax(gm,           ENC - __float_as_int(m0));
        atomicMax(gm + TPB,     ENC - __float_as_int(m1));
        atomicMax(gm + 2 * TPB, ENC - __float_as_int(m2));
        atomicMax(gm + 3 * TPB, ENC - __float_as_int(m3));
        atomicMax(gm + 4 * TPB, ENC - __float_as_int(m4));
        atomicMax(gm + 5 * TPB, ENC - __float_as_int(m5));
        atomicMax(gm + 6 * TPB, ENC - __float_as_int(m6));
        atomicMax(gm + 7 * TPB, ENC - __float_as_int(m7));
    }
    __syncthreads();

    // col mins: combine 4 warps (thread t owns candidate t), -> global encoded
    {
        unsigned a = min(min(scolp[t], scolp[SC + t]),
                         min(scolp[2 * SC + t], scolp[3 * SC + t]));
        atomicMax(g_cmin + b * Nn + cs * SC + t, ENC - (int)a);
    }

    // seg NLL: 32 points per block (warp 0)
    if (t < 32) {
        int idx = bl * 32 + t;
        int lb = s_is64 ? (int)((const long long*)lab)[idx] : ((const int*)lab)[idx];
        float v = prob[idx * NC + lb];
        #pragma unroll
        for (int off = 16; off > 0; off >>= 1)
            v += __shfl_xor_sync(0xffffffffu, v, off);
        if (t == 0) g_fpart[bl] = v;
    }

    // publish: one gpu fence per block (t0), then group tickets
    __syncthreads();
    if (t == 0) {
        __threadfence();
        if (atomicAdd(&g_rowtk[rowg], 1u) == (unsigned)(CSN - 1)) s_rowfin = 1;
        if (atomicAdd(&g_coltk[colg], 1u) == (unsigned)(NQB - 1)) s_colfin = 1;
    }
    __syncthreads();

    if (s_rowfin) {   // row leader: sum 1024 query mins; reset
        int4* base = (int4*)(g_rmin + b * Nn + qblk * QPB);
        float acc = 0.f;
        #pragma unroll
        for (int i = 0; i < QPB / 4 / TPB; i++) {
            int4 v = __ldcg(base + t + i * TPB);
            acc += (__int_as_float(ENC - v.x) + __int_as_float(ENC - v.y)) +
                   (__int_as_float(ENC - v.z) + __int_as_float(ENC - v.w));
            __stcg(base + t + i * TPB, make_int4(0, 0, 0, 0));
        }
        sred[t] = acc;
        __syncthreads();
        #pragma unroll
        for (int s = 64; s > 0; s >>= 1) {
            if (t < s) sred[t] += sred[t + s];
            __syncthreads();
        }
        if (t == 0) {
            g_rowpart[rowg] = sred[0];
            g_rowtk[rowg] = 0u;
            __threadfence();
            if (atomicAdd(&g_ticket, 1u) == (unsigned)(NRG + NCG - 1)) s_last = 1;
        }
        __syncthreads();
    }
    if (s_colfin) {   // col leader: sum 128 candidate mins; reset
        float acc = 0.f;
        if (t < SC / 4) {
            int4* base = (int4*)(g_cmin + b * Nn + cs * SC);
            int4 v = __ldcg(base + t);
            acc = (__int_as_float(ENC - v.x) + __int_as_float(ENC - v.y)) +
                  (__int_as_float(ENC - v.z) + __int_as_float(ENC - v.w));
            __stcg(base + t, make_int4(0, 0, 0, 0));
        }
        sred[t] = acc;
        __syncthreads();
        #pragma unroll
        for (int s = 64; s > 0; s >>= 1) {
            if (t < s) sred[t] += sred[t + s];
            __syncthreads();
        }
        if (t == 0) {
            g_colpart[colg] = sred[0];
            g_coltk[colg] = 0u;
            __threadfence();
            if (atomicAdd(&g_ticket, 1u) == (unsigned)(NRG + NCG - 1)) s_last = 1;
        }
        __syncthreads();
    }

    __syncthreads();
    if (s_last) {     // final deterministic combine (one block, L2 reads)
        float v = __ldcg(&g_colpart[t]) + __ldcg(&g_colpart[t + TPB]);  // 256 col sums
        if (t < NRG) v += __ldcg(&g_rowpart[t]);                        // 32 row sums
        float sp = 0.f;
        #pragma unroll
        for (int k = 0; k < NBLK / TPB; k++)
            sp += __ldcg(&g_fpart[t + k * TPB]);                        // 1024 seg partials
        sred[t] = v - sp;
        __syncthreads();
        #pragma unroll
        for (int s = 64; s > 0; s >>= 1) {
            if (t < s) sred[t] += sred[t + s];
            __syncthreads();
        }
        if (t == 0) {
            out[0] = sred[0] * (1.0f / (float)BN);
            g_ticket = 0u;   // reset for next graph replay
        }
    }
}

extern "C" void kernel_launch(void* const* d_in, const int* in_sizes, int n_in,
                              void* d_out, int out_size) {
    const float* seg_prob  = (const float*)d_in[0];
    const void*  seg_label = (const void*)d_in[1];
    const float* point_rec = (const float*)d_in[2];
    const float* point     = (const float*)d_in[3];

    fused_kernel<<<dim3(CSN, NQB, Bb), TPB>>>(point_rec, point, seg_prob, seg_label,
                                              (float*)d_out);
}